// round 15
// baseline (speedup 1.0000x reference)
#include <cuda_runtime.h>
#include <math.h>

#define T_STEPS 32
#define N_BATCH 16
#define D_DIM   256
#define A_DIM   256
#define F1_DIM  512
#define F2_DIM  256
#define BK 16
#define PAIRS 8   // (n,d) pairs per K1 block

// Scratch (allocation-free rule: __device__ globals)
__device__ float g_s2[T_STEPS * N_BATCH * D_DIM];    // [T,N,D]   512KB
__device__ float g_h1[T_STEPS * N_BATCH * F1_DIM];   // [T,N,F1]  1MB
__device__ float g_part[9 * 256 * 1024];             // split-K partials, 9MB

// ---------------------------------------------------------------------------
// K1: fused SDC-linear + exp-filter + LIF + synapse-filter + pool + s2-LIF.
// 512 blocks (ONE wave), each processes PAIRS=8 (n,d) pairs sequentially:
// weights loaded once per block; xs/sh double-buffered; next-pair x
// register-prefetched during the main loop; epilogue of pair p runs on
// warp (p&7) so it overlaps the next pair's main loop.
// ---------------------------------------------------------------------------
__global__ void __launch_bounds__(256) k_snn_core(
    const float* __restrict__ x,      // [T,N,2,D]
    const float* __restrict__ W_sdc,  // [2,A]
    const float* __restrict__ b_sdc,  // [A]
    const float* __restrict__ w_syn,  // [1]
    const float* __restrict__ W_pool, // [A,1]
    const float* __restrict__ b_pool) // [1]
{
    const int a    = threadIdx.x;
    const int lane = a & 31;
    const int warp = a >> 5;
    const int nd0  = blockIdx.x * PAIRS;

    __shared__ float xs[2][T_STEPS * 2];   // x scalars, double-buffered
    __shared__ float sh[2][T_STEPS][137];  // partials, double-buffered

    // block-invariant parameters (amortized over PAIRS pairs)
    const float w0 = W_sdc[a];
    const float w1 = W_sdc[A_DIM + a];
    const float ba = b_sdc[a];
    const float wp = W_pool[a];
    const float dsyn = 1.0f - 1.0f / (1.0f + expf(-w_syn[0]));
    const float bp = b_pool[0];

    // preload pair 0 x
    if (a < 64) {
        const int n = nd0 >> 8, d = nd0 & 255;
        const int t = a >> 1, c = a & 1;
        xs[0][a] = x[((t * N_BATCH + n) * 2 + c) * D_DIM + d];
    }
    __syncthreads();

    #pragma unroll 1
    for (int p = 0; p < PAIRS; ++p) {
        const int nd  = nd0 + p;
        const int n   = nd >> 8;
        const int d   = nd & 255;
        const int cur = p & 1;

        // prefetch next pair's x into a register (overlaps main loop)
        float xreg = 0.0f;
        if (p + 1 < PAIRS && a < 64) {
            const int nd2 = nd + 1;
            const int n2 = nd2 >> 8, d2 = nd2 & 255;
            const int t = a >> 1, c = a & 1;
            xreg = x[((t * N_BATCH + n2) * 2 + c) * D_DIM + d2];
        }

        float i_s = 0.0f, v = 0.0f, syn = 0.0f;

        #pragma unroll 4
        for (int t = 0; t < T_STEPS; ++t) {
            const float x0 = xs[cur][t * 2 + 0];
            const float x1 = xs[cur][t * 2 + 1];
            const float h  = fmaf(x0, w0, fmaf(x1, w1, ba));

            i_s = fmaf(i_s, 0.5f, h);                     // exp_filter tau=2
            v = fmaf(i_s - v, 0.5f, v);                   // LIF tau=2
            const float s1 = (v >= 1.0f) ? 1.0f : 0.0f;
            v = (s1 != 0.0f) ? 0.0f : v;
            syn = fmaf(syn, dsyn, s1);                    // synapse filter

            float val = syn * wp;
            val += __shfl_down_sync(0xffffffffu, val, 16);
            if (lane < 16) sh[cur][t][(warp << 4) + lane] = val;
        }

        // stage next pair's x (read in main loop only after the barrier)
        if (p + 1 < PAIRS && a < 64) xs[cur ^ 1][a] = xreg;
        __syncthreads();

        // epilogue for pair p on warp (p&7): overlaps next pair's main loop.
        if (warp == (p & 7)) {
            float z0 = 0.0f, z1 = 0.0f, z2 = 0.0f, z3 = 0.0f;
            #pragma unroll
            for (int j = 0; j < 128; j += 4) {
                z0 += sh[cur][lane][j + 0];
                z1 += sh[cur][lane][j + 1];
                z2 += sh[cur][lane][j + 2];
                z3 += sh[cur][lane][j + 3];
            }
            float z = bp + ((z0 + z1) + (z2 + z3));

            float v2 = 0.0f, s_mine = 0.0f;
            #pragma unroll
            for (int t = 0; t < T_STEPS; ++t) {
                const float zt = __shfl_sync(0xffffffffu, z, t);
                v2 = fmaf(zt - v2, 0.5f, v2);
                const float s = (v2 >= 1.0f) ? 1.0f : 0.0f;
                v2 = (s != 0.0f) ? 0.0f : v2;
                if (lane == t) s_mine = s;
            }
            g_s2[(lane * N_BATCH + n) * D_DIM + d] = s_mine;
        }
    }
}

// ---------------------------------------------------------------------------
// K2 GEMM: 64(M) x 128(N) tile, BK=16, 256 threads, 8x4 micro-tile.
// (R11 single-buffer form — measured best.)
// ---------------------------------------------------------------------------
__global__ void __launch_bounds__(256) k_gemm_splitk_w(
    const float* __restrict__ A, const float* __restrict__ B,
    float* __restrict__ P, int M, int K, int N, int Kc)
{
    __shared__ float As[BK][68];    // [k][m] 64 + pad
    __shared__ float Bs[BK][132];   // [k][n] 128 + pad
    const int tid = threadIdx.x;
    const int tx  = tid & 31;
    const int ty  = tid >> 5;
    const int row0 = blockIdx.y * 64;
    const int col0 = blockIdx.x * 128;
    const int kbeg = blockIdx.z * Kc;
    const int kend = kbeg + Kc;

    const int ar = tid >> 2;
    const int ak = (tid & 3) << 2;
    const int bk = tid >> 4;
    const int bn = (tid & 15) << 3;

    float acc[8][4] = {};

    float4 av  = *(const float4*)(A + (row0 + ar) * K + kbeg + ak);
    float4 bv0 = *(const float4*)(B + (kbeg + bk) * N + col0 + bn);
    float4 bv1 = *(const float4*)(B + (kbeg + bk) * N + col0 + bn + 4);

    for (int k0 = kbeg; k0 < kend; k0 += BK) {
        As[ak + 0][ar] = av.x;
        As[ak + 1][ar] = av.y;
        As[ak + 2][ar] = av.z;
        As[ak + 3][ar] = av.w;
        *(float4*)(&Bs[bk][bn])     = bv0;
        *(float4*)(&Bs[bk][bn + 4]) = bv1;
        __syncthreads();

        const int kn = k0 + BK;
        if (kn < kend) {
            av  = *(const float4*)(A + (row0 + ar) * K + kn + ak);
            bv0 = *(const float4*)(B + (kn + bk) * N + col0 + bn);
            bv1 = *(const float4*)(B + (kn + bk) * N + col0 + bn + 4);
        }

        #pragma unroll
        for (int kk = 0; kk < BK; ++kk) {
            const float4 a0 = *(const float4*)(&As[kk][ty << 3]);
            const float4 a1 = *(const float4*)(&As[kk][(ty << 3) + 4]);
            const float4 b  = *(const float4*)(&Bs[kk][tx << 2]);
            acc[0][0] = fmaf(a0.x, b.x, acc[0][0]);
            acc[0][1] = fmaf(a0.x, b.y, acc[0][1]);
            acc[0][2] = fmaf(a0.x, b.z, acc[0][2]);
            acc[0][3] = fmaf(a0.x, b.w, acc[0][3]);
            acc[1][0] = fmaf(a0.y, b.x, acc[1][0]);
            acc[1][1] = fmaf(a0.y, b.y, acc[1][1]);
            acc[1][2] = fmaf(a0.y, b.z, acc[1][2]);
            acc[1][3] = fmaf(a0.y, b.w, acc[1][3]);
            acc[2][0] = fmaf(a0.z, b.x, acc[2][0]);
            acc[2][1] = fmaf(a0.z, b.y, acc[2][1]);
            acc[2][2] = fmaf(a0.z, b.z, acc[2][2]);
            acc[2][3] = fmaf(a0.z, b.w, acc[2][3]);
            acc[3][0] = fmaf(a0.w, b.x, acc[3][0]);
            acc[3][1] = fmaf(a0.w, b.y, acc[3][1]);
            acc[3][2] = fmaf(a0.w, b.z, acc[3][2]);
            acc[3][3] = fmaf(a0.w, b.w, acc[3][3]);
            acc[4][0] = fmaf(a1.x, b.x, acc[4][0]);
            acc[4][1] = fmaf(a1.x, b.y, acc[4][1]);
            acc[4][2] = fmaf(a1.x, b.z, acc[4][2]);
            acc[4][3] = fmaf(a1.x, b.w, acc[4][3]);
            acc[5][0] = fmaf(a1.y, b.x, acc[5][0]);
            acc[5][1] = fmaf(a1.y, b.y, acc[5][1]);
            acc[5][2] = fmaf(a1.y, b.z, acc[5][2]);
            acc[5][3] = fmaf(a1.y, b.w, acc[5][3]);
            acc[6][0] = fmaf(a1.z, b.x, acc[6][0]);
            acc[6][1] = fmaf(a1.z, b.y, acc[6][1]);
            acc[6][2] = fmaf(a1.z, b.z, acc[6][2]);
            acc[6][3] = fmaf(a1.z, b.w, acc[6][3]);
            acc[7][0] = fmaf(a1.w, b.x, acc[7][0]);
            acc[7][1] = fmaf(a1.w, b.y, acc[7][1]);
            acc[7][2] = fmaf(a1.w, b.z, acc[7][2]);
            acc[7][3] = fmaf(a1.w, b.w, acc[7][3]);
        }
        __syncthreads();
    }

    float* Pout = P + blockIdx.z * M * N;
    #pragma unroll
    for (int i = 0; i < 8; ++i) {
        float4 o;
        o.x = acc[i][0]; o.y = acc[i][1]; o.z = acc[i][2]; o.w = acc[i][3];
        *(float4*)(Pout + (row0 + (ty << 3) + i) * N + col0 + (tx << 2)) = o;
    }
}

// ---------------------------------------------------------------------------
// K4 GEMM: 64x64 tile, 256 threads, 4x4 micro (R11 form — measured best).
// ---------------------------------------------------------------------------
__global__ void __launch_bounds__(256) k_gemm_splitk(
    const float* __restrict__ A, const float* __restrict__ B,
    float* __restrict__ P, int M, int K, int N, int Kc)
{
    __shared__ float As[BK][68];
    __shared__ float Bs[BK][64];
    const int tid = threadIdx.x;
    const int tx  = tid & 15;
    const int ty  = tid >> 4;
    const int row0 = blockIdx.y * 64;
    const int col0 = blockIdx.x * 64;
    const int kbeg = blockIdx.z * Kc;
    const int kend = kbeg + Kc;

    const int ar = tid >> 2;
    const int ak = (tid & 3) << 2;
    const int bk = tid >> 4;
    const int bn = (tid & 15) << 2;

    float acc[4][4] = {};

    float4 av = *(const float4*)(A + (row0 + ar) * K + kbeg + ak);
    float4 bv = *(const float4*)(B + (kbeg + bk) * N + col0 + bn);

    for (int k0 = kbeg; k0 < kend; k0 += BK) {
        As[ak + 0][ar] = av.x;
        As[ak + 1][ar] = av.y;
        As[ak + 2][ar] = av.z;
        As[ak + 3][ar] = av.w;
        *(float4*)(&Bs[bk][bn]) = bv;
        __syncthreads();

        const int kn = k0 + BK;
        if (kn < kend) {
            av = *(const float4*)(A + (row0 + ar) * K + kn + ak);
            bv = *(const float4*)(B + (kn + bk) * N + col0 + bn);
        }

        #pragma unroll
        for (int kk = 0; kk < BK; ++kk) {
            const float4 a = *(const float4*)(&As[kk][ty << 2]);
            const float4 b = *(const float4*)(&Bs[kk][tx << 2]);
            acc[0][0] = fmaf(a.x, b.x, acc[0][0]);
            acc[0][1] = fmaf(a.x, b.y, acc[0][1]);
            acc[0][2] = fmaf(a.x, b.z, acc[0][2]);
            acc[0][3] = fmaf(a.x, b.w, acc[0][3]);
            acc[1][0] = fmaf(a.y, b.x, acc[1][0]);
            acc[1][1] = fmaf(a.y, b.y, acc[1][1]);
            acc[1][2] = fmaf(a.y, b.z, acc[1][2]);
            acc[1][3] = fmaf(a.y, b.w, acc[1][3]);
            acc[2][0] = fmaf(a.z, b.x, acc[2][0]);
            acc[2][1] = fmaf(a.z, b.y, acc[2][1]);
            acc[2][2] = fmaf(a.z, b.z, acc[2][2]);
            acc[2][3] = fmaf(a.z, b.w, acc[2][3]);
            acc[3][0] = fmaf(a.w, b.x, acc[3][0]);
            acc[3][1] = fmaf(a.w, b.y, acc[3][1]);
            acc[3][2] = fmaf(a.w, b.z, acc[3][2]);
            acc[3][3] = fmaf(a.w, b.w, acc[3][3]);
        }
        __syncthreads();
    }

    float* Pout = P + blockIdx.z * M * N;
    #pragma unroll
    for (int i = 0; i < 4; ++i) {
        float4 o;
        o.x = acc[i][0]; o.y = acc[i][1]; o.z = acc[i][2]; o.w = acc[i][3];
        *(float4*)(Pout + (row0 + (ty << 2) + i) * N + col0 + (tx << 2)) = o;
    }
}

// ---------------------------------------------------------------------------
// Fused split-K reduce + bias + LIF scan. ILP: all t-sums in registers first.
// ---------------------------------------------------------------------------
template<int S>
__global__ void __launch_bounds__(256) k_reduce_lif(
    const float* __restrict__ P, const float* __restrict__ bias,
    float* __restrict__ out, int F)
{
    const int j  = blockIdx.x * blockDim.x + threadIdx.x;
    const int nb = j / F;
    const int f  = j % F;
    const int MN = T_STEPS * N_BATCH * F;
    const int stride_t = N_BATCH * F;

    float acc[T_STEPS];
    const float b = bias[f];
    #pragma unroll
    for (int t = 0; t < T_STEPS; ++t) acc[t] = b;

    #pragma unroll
    for (int s = 0; s < S; ++s) {
        const float* Ps = P + s * MN + nb * F + f;
        #pragma unroll
        for (int t = 0; t < T_STEPS; ++t)
            acc[t] += Ps[t * stride_t];
    }

    float v = 0.0f;
    float* op = out + nb * F + f;
    #pragma unroll
    for (int t = 0; t < T_STEPS; ++t) {
        v = fmaf(acc[t] - v, 0.5f, v);
        const float sp = (v >= 1.0f) ? 1.0f : 0.0f;
        op[t * stride_t] = sp;
        v = (sp != 0.0f) ? 0.0f : v;
    }
}

// ---------------------------------------------------------------------------
// Tail: reduce(S) + bias + LIF + W_out dot + cumsum. ILP load phase.
// ---------------------------------------------------------------------------
template<int S>
__global__ void __launch_bounds__(256) k_tail(
    const float* __restrict__ P, const float* __restrict__ bias,
    const float* __restrict__ W_out, const float* __restrict__ b_out,
    float* __restrict__ out)
{
    const int nb   = blockIdx.x;
    const int f    = threadIdx.x;
    const int lane = f & 31;
    const int warp = f >> 5;
    const int MN   = T_STEPS * N_BATCH * F2_DIM;
    const int stride_t = N_BATCH * F2_DIM;

    const float b  = bias[f];
    const float w  = W_out[f];
    const float bo = b_out[0];

    float acc[T_STEPS];
    #pragma unroll
    for (int t = 0; t < T_STEPS; ++t) acc[t] = b;
    #pragma unroll
    for (int s = 0; s < S; ++s) {
        const float* Ps = P + s * MN + nb * F2_DIM + f;
        #pragma unroll
        for (int t = 0; t < T_STEPS; ++t)
            acc[t] += Ps[t * stride_t];
    }

    __shared__ float sh[T_STEPS][8];
    float v = 0.0f;
    #pragma unroll
    for (int t = 0; t < T_STEPS; ++t) {
        v = fmaf(acc[t] - v, 0.5f, v);
        const float sp = (v >= 1.0f) ? 1.0f : 0.0f;
        v = (sp != 0.0f) ? 0.0f : v;

        float r = sp * w;
        #pragma unroll
        for (int off = 16; off; off >>= 1)
            r += __shfl_down_sync(0xffffffffu, r, off);
        if (lane == 0) sh[t][warp] = r;
    }
    __syncthreads();

    if (warp == 0) {
        float z = bo;
        #pragma unroll
        for (int w8 = 0; w8 < 8; ++w8) z += sh[lane][w8];
        float a = 0.0f, mine = 0.0f;
        #pragma unroll
        for (int t = 0; t < T_STEPS; ++t) {
            a += __shfl_sync(0xffffffffu, z, t);
            if (lane == t) mine = a;
        }
        out[lane * N_BATCH + nb] = mine;
    }
}

extern "C" void kernel_launch(void* const* d_in, const int* in_sizes, int n_in,
                              void* d_out, int out_size)
{
    const float* x      = (const float*)d_in[0];
    const float* W_sdc  = (const float*)d_in[1];
    const float* b_sdc  = (const float*)d_in[2];
    const float* w_syn  = (const float*)d_in[3];
    const float* W_pool = (const float*)d_in[4];
    const float* b_pool = (const float*)d_in[5];
    const float* W_f1   = (const float*)d_in[6];
    const float* b_f1   = (const float*)d_in[7];
    const float* W_f2   = (const float*)d_in[8];
    const float* b_f2   = (const float*)d_in[9];
    const float* W_out  = (const float*)d_in[10];
    const float* b_out  = (const float*)d_in[11];
    float* out = (float*)d_out;

    float* s2 = nullptr; float* h1 = nullptr; float* part = nullptr;
    cudaGetSymbolAddress((void**)&s2, g_s2);
    cudaGetSymbolAddress((void**)&h1, g_h1);
    cudaGetSymbolAddress((void**)&part, g_part);

    const int M = T_STEPS * N_BATCH;  // 512

    // K1: fused SNN core -> g_s2 [T,N,D].  512 blocks, one wave.
    k_snn_core<<<(N_BATCH * D_DIM) / PAIRS, 256>>>(x, W_sdc, b_sdc, w_syn, W_pool, b_pool);

    // K2: partials of s2 @ W_f1  (M=512, K=256, N=512), S=8, Kc=32 -> 256 blocks
    {
        dim3 grid(F1_DIM / 128, M / 64, 8);
        k_gemm_splitk_w<<<grid, 256>>>(s2, W_f1, part, M, D_DIM, F1_DIM, 32);
    }
    // K3: reduce(8) + bias + LIF -> h1
    k_reduce_lif<8><<<(N_BATCH * F1_DIM) / 256, 256>>>(part, b_f1, h1, F1_DIM);

    // K4: partials of h1 @ W_f2  (M=512, K=512, N=256), S=8, Kc=64 -> 256 blocks
    {
        dim3 grid(F2_DIM / 64, M / 64, 8);
        k_gemm_splitk<<<grid, 256>>>(h1, W_f2, part, M, F1_DIM, F2_DIM, 64);
    }
    // K5: fused reduce(8) + LIF + readout dot + cumsum -> out
    k_tail<8><<<N_BATCH, 256>>>(part, b_f2, W_out, b_out, out);
}

// round 16
// speedup vs baseline: 1.1484x; 1.1484x over previous
#include <cuda_runtime.h>
#include <math.h>

#define T_STEPS 32
#define N_BATCH 16
#define D_DIM   256
#define A_DIM   256
#define F1_DIM  512
#define F2_DIM  256
#define BK 16

// Scratch (allocation-free rule: __device__ globals)
__device__ float g_s2[T_STEPS * N_BATCH * D_DIM];    // [T,N,D]   512KB
__device__ float g_h1[T_STEPS * N_BATCH * F1_DIM];   // [T,N,F1]  1MB
__device__ float g_part[9 * 256 * 1024];             // split-K partials, 9MB

// ---------------------------------------------------------------------------
// K1: fused SDC-linear + exp-filter + LIF + synapse-filter + pool + s2-LIF.
// R11 champion form: block=(n,d) (4096 blocks, max parallelism), smem-x
// preload, 1-shfl reduce into [32][137], ONE barrier, warp-0 epilogue.
// Only delta vs R11: main-loop unroll 4 -> 8.
// ---------------------------------------------------------------------------
__global__ void __launch_bounds__(256) k_snn_core(
    const float* __restrict__ x,      // [T,N,2,D]
    const float* __restrict__ W_sdc,  // [2,A]
    const float* __restrict__ b_sdc,  // [A]
    const float* __restrict__ w_syn,  // [1]
    const float* __restrict__ W_pool, // [A,1]
    const float* __restrict__ b_pool) // [1]
{
    const int a    = threadIdx.x;
    const int nd   = blockIdx.x;
    const int n    = nd >> 8;   // D = 256
    const int d    = nd & 255;
    const int lane = a & 31;
    const int warp = a >> 5;

    __shared__ float xs[T_STEPS * 2];    // x scalars for this (n,d)
    __shared__ float sh[T_STEPS][137];   // stride 137: conflict-free both phases

    if (a < 64) {
        const int t = a >> 1, c = a & 1;
        xs[a] = x[((t * N_BATCH + n) * 2 + c) * D_DIM + d];
    }

    const float w0 = W_sdc[a];
    const float w1 = W_sdc[A_DIM + a];
    const float ba = b_sdc[a];
    const float wp = W_pool[a];
    const float dsyn = 1.0f - 1.0f / (1.0f + expf(-w_syn[0]));
    const float bp = b_pool[0];

    float i_s = 0.0f, v = 0.0f, syn = 0.0f;
    __syncthreads();

    #pragma unroll 8
    for (int t = 0; t < T_STEPS; ++t) {
        const float x0 = xs[t * 2 + 0];
        const float x1 = xs[t * 2 + 1];
        const float h  = fmaf(x0, w0, fmaf(x1, w1, ba));

        i_s = fmaf(i_s, 0.5f, h);                     // exp_filter tau=2
        v = fmaf(i_s - v, 0.5f, v);                   // LIF tau=2
        const float s1 = (v >= 1.0f) ? 1.0f : 0.0f;
        v = (s1 != 0.0f) ? 0.0f : v;
        syn = fmaf(syn, dsyn, s1);                    // synapse filter

        float val = syn * wp;
        val += __shfl_down_sync(0xffffffffu, val, 16);
        if (lane < 16) sh[t][(warp << 4) + lane] = val;   // 16 partials/warp
    }
    __syncthreads();

    if (warp == 0) {
        // lane == t : sum 128 partials with 4-way ILP
        float z0 = 0.0f, z1 = 0.0f, z2 = 0.0f, z3 = 0.0f;
        #pragma unroll
        for (int j = 0; j < 128; j += 4) {
            z0 += sh[lane][j + 0];
            z1 += sh[lane][j + 1];
            z2 += sh[lane][j + 2];
            z3 += sh[lane][j + 3];
        }
        float z = bp + ((z0 + z1) + (z2 + z3));

        float v2 = 0.0f, s_mine = 0.0f;
        #pragma unroll
        for (int t = 0; t < T_STEPS; ++t) {
            const float zt = __shfl_sync(0xffffffffu, z, t);
            v2 = fmaf(zt - v2, 0.5f, v2);
            const float s = (v2 >= 1.0f) ? 1.0f : 0.0f;
            v2 = (s != 0.0f) ? 0.0f : v2;
            if (lane == t) s_mine = s;
        }
        g_s2[(lane * N_BATCH + n) * D_DIM + d] = s_mine;
    }
}

// ---------------------------------------------------------------------------
// K2 GEMM: 64(M) x 128(N) tile, BK=16, 256 threads, 8x4 micro-tile.
// 3 LDS.128 per 32 FMA, 256-block grid, 8 warps. Global->reg prefetch.
// (R11 form — measured best.)
// ---------------------------------------------------------------------------
__global__ void __launch_bounds__(256) k_gemm_splitk_w(
    const float* __restrict__ A, const float* __restrict__ B,
    float* __restrict__ P, int M, int K, int N, int Kc)
{
    __shared__ float As[BK][68];    // [k][m] 64 + pad
    __shared__ float Bs[BK][132];   // [k][n] 128 + pad
    const int tid = threadIdx.x;
    const int tx  = tid & 31;
    const int ty  = tid >> 5;
    const int row0 = blockIdx.y * 64;
    const int col0 = blockIdx.x * 128;
    const int kbeg = blockIdx.z * Kc;
    const int kend = kbeg + Kc;

    const int ar = tid >> 2;
    const int ak = (tid & 3) << 2;
    const int bk = tid >> 4;
    const int bn = (tid & 15) << 3;

    float acc[8][4] = {};

    float4 av  = *(const float4*)(A + (row0 + ar) * K + kbeg + ak);
    float4 bv0 = *(const float4*)(B + (kbeg + bk) * N + col0 + bn);
    float4 bv1 = *(const float4*)(B + (kbeg + bk) * N + col0 + bn + 4);

    for (int k0 = kbeg; k0 < kend; k0 += BK) {
        As[ak + 0][ar] = av.x;
        As[ak + 1][ar] = av.y;
        As[ak + 2][ar] = av.z;
        As[ak + 3][ar] = av.w;
        *(float4*)(&Bs[bk][bn])     = bv0;
        *(float4*)(&Bs[bk][bn + 4]) = bv1;
        __syncthreads();

        const int kn = k0 + BK;
        if (kn < kend) {
            av  = *(const float4*)(A + (row0 + ar) * K + kn + ak);
            bv0 = *(const float4*)(B + (kn + bk) * N + col0 + bn);
            bv1 = *(const float4*)(B + (kn + bk) * N + col0 + bn + 4);
        }

        #pragma unroll
        for (int kk = 0; kk < BK; ++kk) {
            const float4 a0 = *(const float4*)(&As[kk][ty << 3]);
            const float4 a1 = *(const float4*)(&As[kk][(ty << 3) + 4]);
            const float4 b  = *(const float4*)(&Bs[kk][tx << 2]);
            acc[0][0] = fmaf(a0.x, b.x, acc[0][0]);
            acc[0][1] = fmaf(a0.x, b.y, acc[0][1]);
            acc[0][2] = fmaf(a0.x, b.z, acc[0][2]);
            acc[0][3] = fmaf(a0.x, b.w, acc[0][3]);
            acc[1][0] = fmaf(a0.y, b.x, acc[1][0]);
            acc[1][1] = fmaf(a0.y, b.y, acc[1][1]);
            acc[1][2] = fmaf(a0.y, b.z, acc[1][2]);
            acc[1][3] = fmaf(a0.y, b.w, acc[1][3]);
            acc[2][0] = fmaf(a0.z, b.x, acc[2][0]);
            acc[2][1] = fmaf(a0.z, b.y, acc[2][1]);
            acc[2][2] = fmaf(a0.z, b.z, acc[2][2]);
            acc[2][3] = fmaf(a0.z, b.w, acc[2][3]);
            acc[3][0] = fmaf(a0.w, b.x, acc[3][0]);
            acc[3][1] = fmaf(a0.w, b.y, acc[3][1]);
            acc[3][2] = fmaf(a0.w, b.z, acc[3][2]);
            acc[3][3] = fmaf(a0.w, b.w, acc[3][3]);
            acc[4][0] = fmaf(a1.x, b.x, acc[4][0]);
            acc[4][1] = fmaf(a1.x, b.y, acc[4][1]);
            acc[4][2] = fmaf(a1.x, b.z, acc[4][2]);
            acc[4][3] = fmaf(a1.x, b.w, acc[4][3]);
            acc[5][0] = fmaf(a1.y, b.x, acc[5][0]);
            acc[5][1] = fmaf(a1.y, b.y, acc[5][1]);
            acc[5][2] = fmaf(a1.y, b.z, acc[5][2]);
            acc[5][3] = fmaf(a1.y, b.w, acc[5][3]);
            acc[6][0] = fmaf(a1.z, b.x, acc[6][0]);
            acc[6][1] = fmaf(a1.z, b.y, acc[6][1]);
            acc[6][2] = fmaf(a1.z, b.z, acc[6][2]);
            acc[6][3] = fmaf(a1.z, b.w, acc[6][3]);
            acc[7][0] = fmaf(a1.w, b.x, acc[7][0]);
            acc[7][1] = fmaf(a1.w, b.y, acc[7][1]);
            acc[7][2] = fmaf(a1.w, b.z, acc[7][2]);
            acc[7][3] = fmaf(a1.w, b.w, acc[7][3]);
        }
        __syncthreads();
    }

    float* Pout = P + blockIdx.z * M * N;
    #pragma unroll
    for (int i = 0; i < 8; ++i) {
        float4 o;
        o.x = acc[i][0]; o.y = acc[i][1]; o.z = acc[i][2]; o.w = acc[i][3];
        *(float4*)(Pout + (row0 + (ty << 3) + i) * N + col0 + (tx << 2)) = o;
    }
}

// ---------------------------------------------------------------------------
// K4 GEMM: 64x64 tile, 256 threads, 4x4 micro (R11 form — measured best).
// ---------------------------------------------------------------------------
__global__ void __launch_bounds__(256) k_gemm_splitk(
    const float* __restrict__ A, const float* __restrict__ B,
    float* __restrict__ P, int M, int K, int N, int Kc)
{
    __shared__ float As[BK][68];
    __shared__ float Bs[BK][64];
    const int tid = threadIdx.x;
    const int tx  = tid & 15;
    const int ty  = tid >> 4;
    const int row0 = blockIdx.y * 64;
    const int col0 = blockIdx.x * 64;
    const int kbeg = blockIdx.z * Kc;
    const int kend = kbeg + Kc;

    const int ar = tid >> 2;
    const int ak = (tid & 3) << 2;
    const int bk = tid >> 4;
    const int bn = (tid & 15) << 2;

    float acc[4][4] = {};

    float4 av = *(const float4*)(A + (row0 + ar) * K + kbeg + ak);
    float4 bv = *(const float4*)(B + (kbeg + bk) * N + col0 + bn);

    for (int k0 = kbeg; k0 < kend; k0 += BK) {
        As[ak + 0][ar] = av.x;
        As[ak + 1][ar] = av.y;
        As[ak + 2][ar] = av.z;
        As[ak + 3][ar] = av.w;
        *(float4*)(&Bs[bk][bn]) = bv;
        __syncthreads();

        const int kn = k0 + BK;
        if (kn < kend) {
            av = *(const float4*)(A + (row0 + ar) * K + kn + ak);
            bv = *(const float4*)(B + (kn + bk) * N + col0 + bn);
        }

        #pragma unroll
        for (int kk = 0; kk < BK; ++kk) {
            const float4 a = *(const float4*)(&As[kk][ty << 2]);
            const float4 b = *(const float4*)(&Bs[kk][tx << 2]);
            acc[0][0] = fmaf(a.x, b.x, acc[0][0]);
            acc[0][1] = fmaf(a.x, b.y, acc[0][1]);
            acc[0][2] = fmaf(a.x, b.z, acc[0][2]);
            acc[0][3] = fmaf(a.x, b.w, acc[0][3]);
            acc[1][0] = fmaf(a.y, b.x, acc[1][0]);
            acc[1][1] = fmaf(a.y, b.y, acc[1][1]);
            acc[1][2] = fmaf(a.y, b.z, acc[1][2]);
            acc[1][3] = fmaf(a.y, b.w, acc[1][3]);
            acc[2][0] = fmaf(a.z, b.x, acc[2][0]);
            acc[2][1] = fmaf(a.z, b.y, acc[2][1]);
            acc[2][2] = fmaf(a.z, b.z, acc[2][2]);
            acc[2][3] = fmaf(a.z, b.w, acc[2][3]);
            acc[3][0] = fmaf(a.w, b.x, acc[3][0]);
            acc[3][1] = fmaf(a.w, b.y, acc[3][1]);
            acc[3][2] = fmaf(a.w, b.z, acc[3][2]);
            acc[3][3] = fmaf(a.w, b.w, acc[3][3]);
        }
        __syncthreads();
    }

    float* Pout = P + blockIdx.z * M * N;
    #pragma unroll
    for (int i = 0; i < 4; ++i) {
        float4 o;
        o.x = acc[i][0]; o.y = acc[i][1]; o.z = acc[i][2]; o.w = acc[i][3];
        *(float4*)(Pout + (row0 + (ty << 2) + i) * N + col0 + (tx << 2)) = o;
    }
}

// ---------------------------------------------------------------------------
// Fused split-K reduce + bias + LIF scan. ILP: all t-sums in registers first.
// ---------------------------------------------------------------------------
template<int S>
__global__ void __launch_bounds__(256) k_reduce_lif(
    const float* __restrict__ P, const float* __restrict__ bias,
    float* __restrict__ out, int F)
{
    const int j  = blockIdx.x * blockDim.x + threadIdx.x;
    const int nb = j / F;
    const int f  = j % F;
    const int MN = T_STEPS * N_BATCH * F;
    const int stride_t = N_BATCH * F;

    float acc[T_STEPS];
    const float b = bias[f];
    #pragma unroll
    for (int t = 0; t < T_STEPS; ++t) acc[t] = b;

    #pragma unroll
    for (int s = 0; s < S; ++s) {
        const float* Ps = P + s * MN + nb * F + f;
        #pragma unroll
        for (int t = 0; t < T_STEPS; ++t)
            acc[t] += Ps[t * stride_t];
    }

    float v = 0.0f;
    float* op = out + nb * F + f;
    #pragma unroll
    for (int t = 0; t < T_STEPS; ++t) {
        v = fmaf(acc[t] - v, 0.5f, v);
        const float sp = (v >= 1.0f) ? 1.0f : 0.0f;
        op[t * stride_t] = sp;
        v = (sp != 0.0f) ? 0.0f : v;
    }
}

// ---------------------------------------------------------------------------
// Tail: reduce(S) + bias + LIF + W_out dot + cumsum. ILP load phase.
// ---------------------------------------------------------------------------
template<int S>
__global__ void __launch_bounds__(256) k_tail(
    const float* __restrict__ P, const float* __restrict__ bias,
    const float* __restrict__ W_out, const float* __restrict__ b_out,
    float* __restrict__ out)
{
    const int nb   = blockIdx.x;
    const int f    = threadIdx.x;
    const int lane = f & 31;
    const int warp = f >> 5;
    const int MN   = T_STEPS * N_BATCH * F2_DIM;
    const int stride_t = N_BATCH * F2_DIM;

    const float b  = bias[f];
    const float w  = W_out[f];
    const float bo = b_out[0];

    float acc[T_STEPS];
    #pragma unroll
    for (int t = 0; t < T_STEPS; ++t) acc[t] = b;
    #pragma unroll
    for (int s = 0; s < S; ++s) {
        const float* Ps = P + s * MN + nb * F2_DIM + f;
        #pragma unroll
        for (int t = 0; t < T_STEPS; ++t)
            acc[t] += Ps[t * stride_t];
    }

    __shared__ float sh[T_STEPS][8];
    float v = 0.0f;
    #pragma unroll
    for (int t = 0; t < T_STEPS; ++t) {
        v = fmaf(acc[t] - v, 0.5f, v);
        const float sp = (v >= 1.0f) ? 1.0f : 0.0f;
        v = (sp != 0.0f) ? 0.0f : v;

        float r = sp * w;
        #pragma unroll
        for (int off = 16; off; off >>= 1)
            r += __shfl_down_sync(0xffffffffu, r, off);
        if (lane == 0) sh[t][warp] = r;
    }
    __syncthreads();

    if (warp == 0) {
        float z = bo;
        #pragma unroll
        for (int w8 = 0; w8 < 8; ++w8) z += sh[lane][w8];
        float a = 0.0f, mine = 0.0f;
        #pragma unroll
        for (int t = 0; t < T_STEPS; ++t) {
            a += __shfl_sync(0xffffffffu, z, t);
            if (lane == t) mine = a;
        }
        out[lane * N_BATCH + nb] = mine;
    }
}

extern "C" void kernel_launch(void* const* d_in, const int* in_sizes, int n_in,
                              void* d_out, int out_size)
{
    const float* x      = (const float*)d_in[0];
    const float* W_sdc  = (const float*)d_in[1];
    const float* b_sdc  = (const float*)d_in[2];
    const float* w_syn  = (const float*)d_in[3];
    const float* W_pool = (const float*)d_in[4];
    const float* b_pool = (const float*)d_in[5];
    const float* W_f1   = (const float*)d_in[6];
    const float* b_f1   = (const float*)d_in[7];
    const float* W_f2   = (const float*)d_in[8];
    const float* b_f2   = (const float*)d_in[9];
    const float* W_out  = (const float*)d_in[10];
    const float* b_out  = (const float*)d_in[11];
    float* out = (float*)d_out;

    float* s2 = nullptr; float* h1 = nullptr; float* part = nullptr;
    cudaGetSymbolAddress((void**)&s2, g_s2);
    cudaGetSymbolAddress((void**)&h1, g_h1);
    cudaGetSymbolAddress((void**)&part, g_part);

    const int M = T_STEPS * N_BATCH;  // 512

    // K1: fused SNN core -> g_s2 [T,N,D].  4096 blocks (max parallelism).
    k_snn_core<<<N_BATCH * D_DIM, 256>>>(x, W_sdc, b_sdc, w_syn, W_pool, b_pool);

    // K2: partials of s2 @ W_f1  (M=512, K=256, N=512), S=8, Kc=32 -> 256 blocks
    {
        dim3 grid(F1_DIM / 128, M / 64, 8);
        k_gemm_splitk_w<<<grid, 256>>>(s2, W_f1, part, M, D_DIM, F1_DIM, 32);
    }
    // K3: reduce(8) + bias + LIF -> h1
    k_reduce_lif<8><<<(N_BATCH * F1_DIM) / 256, 256>>>(part, b_f1, h1, F1_DIM);

    // K4: partials of h1 @ W_f2  (M=512, K=512, N=256), S=8, Kc=64 -> 256 blocks
    {
        dim3 grid(F2_DIM / 64, M / 64, 8);
        k_gemm_splitk<<<grid, 256>>>(h1, W_f2, part, M, F1_DIM, F2_DIM, 64);
    }
    // K5: fused reduce(8) + LIF + readout dot + cumsum -> out
    k_tail<8><<<N_BATCH, 256>>>(part, b_f2, W_out, b_out, out);
}

// round 17
// speedup vs baseline: 1.2183x; 1.0609x over previous
#include <cuda_runtime.h>
#include <math.h>

#define T_STEPS 32
#define N_BATCH 16
#define D_DIM   256
#define A_DIM   256
#define F1_DIM  512
#define F2_DIM  256
#define BK 16

// Scratch (allocation-free rule: __device__ globals)
__device__ float g_s2[T_STEPS * N_BATCH * D_DIM];    // [T,N,D]   512KB
__device__ float g_h1[T_STEPS * N_BATCH * F1_DIM];   // [T,N,F1]  1MB
__device__ float g_part[9 * 256 * 1024];             // split-K partials, 9MB

#if defined(__CUDA_ARCH__) && (__CUDA_ARCH__ >= 900)
#define PDL_SYNC()    cudaGridDependencySynchronize()
#define PDL_TRIGGER() cudaTriggerProgrammaticLaunchCompletion()
#else
#define PDL_SYNC()
#define PDL_TRIGGER()
#endif

// ---------------------------------------------------------------------------
// K1: fused SDC-linear + exp-filter + LIF + synapse-filter + pool + s2-LIF.
// R11 champion form verbatim. Trigger fires after stores so K2 can spin up.
// ---------------------------------------------------------------------------
__global__ void __launch_bounds__(256) k_snn_core(
    const float* __restrict__ x,      // [T,N,2,D]
    const float* __restrict__ W_sdc,  // [2,A]
    const float* __restrict__ b_sdc,  // [A]
    const float* __restrict__ w_syn,  // [1]
    const float* __restrict__ W_pool, // [A,1]
    const float* __restrict__ b_pool) // [1]
{
    const int a    = threadIdx.x;
    const int nd   = blockIdx.x;
    const int n    = nd >> 8;   // D = 256
    const int d    = nd & 255;
    const int lane = a & 31;
    const int warp = a >> 5;

    __shared__ float xs[T_STEPS * 2];    // x scalars for this (n,d)
    __shared__ float sh[T_STEPS][137];   // stride 137: conflict-free both phases

    if (a < 64) {
        const int t = a >> 1, c = a & 1;
        xs[a] = x[((t * N_BATCH + n) * 2 + c) * D_DIM + d];
    }

    const float w0 = W_sdc[a];
    const float w1 = W_sdc[A_DIM + a];
    const float ba = b_sdc[a];
    const float wp = W_pool[a];
    const float dsyn = 1.0f - 1.0f / (1.0f + expf(-w_syn[0]));
    const float bp = b_pool[0];

    float i_s = 0.0f, v = 0.0f, syn = 0.0f;
    __syncthreads();

    #pragma unroll 4
    for (int t = 0; t < T_STEPS; ++t) {
        const float x0 = xs[t * 2 + 0];
        const float x1 = xs[t * 2 + 1];
        const float h  = fmaf(x0, w0, fmaf(x1, w1, ba));

        i_s = fmaf(i_s, 0.5f, h);                     // exp_filter tau=2
        v = fmaf(i_s - v, 0.5f, v);                   // LIF tau=2
        const float s1 = (v >= 1.0f) ? 1.0f : 0.0f;
        v = (s1 != 0.0f) ? 0.0f : v;
        syn = fmaf(syn, dsyn, s1);                    // synapse filter

        float val = syn * wp;
        val += __shfl_down_sync(0xffffffffu, val, 16);
        if (lane < 16) sh[t][(warp << 4) + lane] = val;   // 16 partials/warp
    }
    __syncthreads();

    if (warp == 0) {
        float z0 = 0.0f, z1 = 0.0f, z2 = 0.0f, z3 = 0.0f;
        #pragma unroll
        for (int j = 0; j < 128; j += 4) {
            z0 += sh[lane][j + 0];
            z1 += sh[lane][j + 1];
            z2 += sh[lane][j + 2];
            z3 += sh[lane][j + 3];
        }
        float z = bp + ((z0 + z1) + (z2 + z3));

        float v2 = 0.0f, s_mine = 0.0f;
        #pragma unroll
        for (int t = 0; t < T_STEPS; ++t) {
            const float zt = __shfl_sync(0xffffffffu, z, t);
            v2 = fmaf(zt - v2, 0.5f, v2);
            const float s = (v2 >= 1.0f) ? 1.0f : 0.0f;
            v2 = (s != 0.0f) ? 0.0f : v2;
            if (lane == t) s_mine = s;
        }
        g_s2[(lane * N_BATCH + n) * D_DIM + d] = s_mine;
    }
    PDL_TRIGGER();
}

// ---------------------------------------------------------------------------
// K2 GEMM: 64(M) x 128(N) tile, BK=16, 256 threads, 8x4 micro-tile.
// PDL: B (weights) prefetched BEFORE grid-dependency sync; A after.
// ---------------------------------------------------------------------------
__global__ void __launch_bounds__(256) k_gemm_splitk_w(
    const float* __restrict__ A, const float* __restrict__ B,
    float* __restrict__ P, int M, int K, int N, int Kc)
{
    __shared__ float As[BK][68];    // [k][m] 64 + pad
    __shared__ float Bs[BK][132];   // [k][n] 128 + pad
    const int tid = threadIdx.x;
    const int tx  = tid & 31;
    const int ty  = tid >> 5;
    const int row0 = blockIdx.y * 64;
    const int col0 = blockIdx.x * 128;
    const int kbeg = blockIdx.z * Kc;
    const int kend = kbeg + Kc;

    const int ar = tid >> 2;
    const int ak = (tid & 3) << 2;
    const int bk = tid >> 4;
    const int bn = (tid & 15) << 3;

    float acc[8][4] = {};

    // independent prologue: weights
    float4 bv0 = *(const float4*)(B + (kbeg + bk) * N + col0 + bn);
    float4 bv1 = *(const float4*)(B + (kbeg + bk) * N + col0 + bn + 4);
    PDL_SYNC();
    // dependent load
    float4 av  = *(const float4*)(A + (row0 + ar) * K + kbeg + ak);

    for (int k0 = kbeg; k0 < kend; k0 += BK) {
        As[ak + 0][ar] = av.x;
        As[ak + 1][ar] = av.y;
        As[ak + 2][ar] = av.z;
        As[ak + 3][ar] = av.w;
        *(float4*)(&Bs[bk][bn])     = bv0;
        *(float4*)(&Bs[bk][bn + 4]) = bv1;
        __syncthreads();

        const int kn = k0 + BK;
        if (kn < kend) {
            av  = *(const float4*)(A + (row0 + ar) * K + kn + ak);
            bv0 = *(const float4*)(B + (kn + bk) * N + col0 + bn);
            bv1 = *(const float4*)(B + (kn + bk) * N + col0 + bn + 4);
        }

        #pragma unroll
        for (int kk = 0; kk < BK; ++kk) {
            const float4 a0 = *(const float4*)(&As[kk][ty << 3]);
            const float4 a1 = *(const float4*)(&As[kk][(ty << 3) + 4]);
            const float4 b  = *(const float4*)(&Bs[kk][tx << 2]);
            acc[0][0] = fmaf(a0.x, b.x, acc[0][0]);
            acc[0][1] = fmaf(a0.x, b.y, acc[0][1]);
            acc[0][2] = fmaf(a0.x, b.z, acc[0][2]);
            acc[0][3] = fmaf(a0.x, b.w, acc[0][3]);
            acc[1][0] = fmaf(a0.y, b.x, acc[1][0]);
            acc[1][1] = fmaf(a0.y, b.y, acc[1][1]);
            acc[1][2] = fmaf(a0.y, b.z, acc[1][2]);
            acc[1][3] = fmaf(a0.y, b.w, acc[1][3]);
            acc[2][0] = fmaf(a0.z, b.x, acc[2][0]);
            acc[2][1] = fmaf(a0.z, b.y, acc[2][1]);
            acc[2][2] = fmaf(a0.z, b.z, acc[2][2]);
            acc[2][3] = fmaf(a0.z, b.w, acc[2][3]);
            acc[3][0] = fmaf(a0.w, b.x, acc[3][0]);
            acc[3][1] = fmaf(a0.w, b.y, acc[3][1]);
            acc[3][2] = fmaf(a0.w, b.z, acc[3][2]);
            acc[3][3] = fmaf(a0.w, b.w, acc[3][3]);
            acc[4][0] = fmaf(a1.x, b.x, acc[4][0]);
            acc[4][1] = fmaf(a1.x, b.y, acc[4][1]);
            acc[4][2] = fmaf(a1.x, b.z, acc[4][2]);
            acc[4][3] = fmaf(a1.x, b.w, acc[4][3]);
            acc[5][0] = fmaf(a1.y, b.x, acc[5][0]);
            acc[5][1] = fmaf(a1.y, b.y, acc[5][1]);
            acc[5][2] = fmaf(a1.y, b.z, acc[5][2]);
            acc[5][3] = fmaf(a1.y, b.w, acc[5][3]);
            acc[6][0] = fmaf(a1.z, b.x, acc[6][0]);
            acc[6][1] = fmaf(a1.z, b.y, acc[6][1]);
            acc[6][2] = fmaf(a1.z, b.z, acc[6][2]);
            acc[6][3] = fmaf(a1.z, b.w, acc[6][3]);
            acc[7][0] = fmaf(a1.w, b.x, acc[7][0]);
            acc[7][1] = fmaf(a1.w, b.y, acc[7][1]);
            acc[7][2] = fmaf(a1.w, b.z, acc[7][2]);
            acc[7][3] = fmaf(a1.w, b.w, acc[7][3]);
        }
        __syncthreads();
    }

    float* Pout = P + blockIdx.z * M * N;
    #pragma unroll
    for (int i = 0; i < 8; ++i) {
        float4 o;
        o.x = acc[i][0]; o.y = acc[i][1]; o.z = acc[i][2]; o.w = acc[i][3];
        *(float4*)(Pout + (row0 + (ty << 3) + i) * N + col0 + (tx << 2)) = o;
    }
    PDL_TRIGGER();
}

// ---------------------------------------------------------------------------
// K4 GEMM: 64x64 tile, 256 threads, 4x4 micro. PDL: B before sync, A after.
// ---------------------------------------------------------------------------
__global__ void __launch_bounds__(256) k_gemm_splitk(
    const float* __restrict__ A, const float* __restrict__ B,
    float* __restrict__ P, int M, int K, int N, int Kc)
{
    __shared__ float As[BK][68];
    __shared__ float Bs[BK][64];
    const int tid = threadIdx.x;
    const int tx  = tid & 15;
    const int ty  = tid >> 4;
    const int row0 = blockIdx.y * 64;
    const int col0 = blockIdx.x * 64;
    const int kbeg = blockIdx.z * Kc;
    const int kend = kbeg + Kc;

    const int ar = tid >> 2;
    const int ak = (tid & 3) << 2;
    const int bk = tid >> 4;
    const int bn = (tid & 15) << 2;

    float acc[4][4] = {};

    float4 bv = *(const float4*)(B + (kbeg + bk) * N + col0 + bn);
    PDL_SYNC();
    float4 av = *(const float4*)(A + (row0 + ar) * K + kbeg + ak);

    for (int k0 = kbeg; k0 < kend; k0 += BK) {
        As[ak + 0][ar] = av.x;
        As[ak + 1][ar] = av.y;
        As[ak + 2][ar] = av.z;
        As[ak + 3][ar] = av.w;
        *(float4*)(&Bs[bk][bn]) = bv;
        __syncthreads();

        const int kn = k0 + BK;
        if (kn < kend) {
            av = *(const float4*)(A + (row0 + ar) * K + kn + ak);
            bv = *(const float4*)(B + (kn + bk) * N + col0 + bn);
        }

        #pragma unroll
        for (int kk = 0; kk < BK; ++kk) {
            const float4 a = *(const float4*)(&As[kk][ty << 2]);
            const float4 b = *(const float4*)(&Bs[kk][tx << 2]);
            acc[0][0] = fmaf(a.x, b.x, acc[0][0]);
            acc[0][1] = fmaf(a.x, b.y, acc[0][1]);
            acc[0][2] = fmaf(a.x, b.z, acc[0][2]);
            acc[0][3] = fmaf(a.x, b.w, acc[0][3]);
            acc[1][0] = fmaf(a.y, b.x, acc[1][0]);
            acc[1][1] = fmaf(a.y, b.y, acc[1][1]);
            acc[1][2] = fmaf(a.y, b.z, acc[1][2]);
            acc[1][3] = fmaf(a.y, b.w, acc[1][3]);
            acc[2][0] = fmaf(a.z, b.x, acc[2][0]);
            acc[2][1] = fmaf(a.z, b.y, acc[2][1]);
            acc[2][2] = fmaf(a.z, b.z, acc[2][2]);
            acc[2][3] = fmaf(a.z, b.w, acc[2][3]);
            acc[3][0] = fmaf(a.w, b.x, acc[3][0]);
            acc[3][1] = fmaf(a.w, b.y, acc[3][1]);
            acc[3][2] = fmaf(a.w, b.z, acc[3][2]);
            acc[3][3] = fmaf(a.w, b.w, acc[3][3]);
        }
        __syncthreads();
    }

    float* Pout = P + blockIdx.z * M * N;
    #pragma unroll
    for (int i = 0; i < 4; ++i) {
        float4 o;
        o.x = acc[i][0]; o.y = acc[i][1]; o.z = acc[i][2]; o.w = acc[i][3];
        *(float4*)(Pout + (row0 + (ty << 2) + i) * N + col0 + (tx << 2)) = o;
    }
    PDL_TRIGGER();
}

// ---------------------------------------------------------------------------
// Fused split-K reduce + bias + LIF scan. PDL: bias before sync, P after.
// ---------------------------------------------------------------------------
template<int S>
__global__ void __launch_bounds__(256) k_reduce_lif(
    const float* __restrict__ P, const float* __restrict__ bias,
    float* __restrict__ out, int F)
{
    const int j  = blockIdx.x * blockDim.x + threadIdx.x;
    const int nb = j / F;
    const int f  = j % F;
    const int MN = T_STEPS * N_BATCH * F;
    const int stride_t = N_BATCH * F;

    float acc[T_STEPS];
    const float b = bias[f];
    #pragma unroll
    for (int t = 0; t < T_STEPS; ++t) acc[t] = b;

    PDL_SYNC();

    #pragma unroll
    for (int s = 0; s < S; ++s) {
        const float* Ps = P + s * MN + nb * F + f;
        #pragma unroll
        for (int t = 0; t < T_STEPS; ++t)
            acc[t] += Ps[t * stride_t];
    }

    float v = 0.0f;
    float* op = out + nb * F + f;
    #pragma unroll
    for (int t = 0; t < T_STEPS; ++t) {
        v = fmaf(acc[t] - v, 0.5f, v);
        const float sp = (v >= 1.0f) ? 1.0f : 0.0f;
        op[t * stride_t] = sp;
        v = (sp != 0.0f) ? 0.0f : v;
    }
    PDL_TRIGGER();
}

// ---------------------------------------------------------------------------
// Tail: reduce(S) + bias + LIF + W_out dot + cumsum. PDL-aware prologue.
// ---------------------------------------------------------------------------
template<int S>
__global__ void __launch_bounds__(256) k_tail(
    const float* __restrict__ P, const float* __restrict__ bias,
    const float* __restrict__ W_out, const float* __restrict__ b_out,
    float* __restrict__ out)
{
    const int nb   = blockIdx.x;
    const int f    = threadIdx.x;
    const int lane = f & 31;
    const int warp = f >> 5;
    const int MN   = T_STEPS * N_BATCH * F2_DIM;
    const int stride_t = N_BATCH * F2_DIM;

    const float b  = bias[f];
    const float w  = W_out[f];
    const float bo = b_out[0];

    float acc[T_STEPS];
    #pragma unroll
    for (int t = 0; t < T_STEPS; ++t) acc[t] = b;

    PDL_SYNC();

    #pragma unroll
    for (int s = 0; s < S; ++s) {
        const float* Ps = P + s * MN + nb * F2_DIM + f;
        #pragma unroll
        for (int t = 0; t < T_STEPS; ++t)
            acc[t] += Ps[t * stride_t];
    }

    __shared__ float sh[T_STEPS][8];
    float v = 0.0f;
    #pragma unroll
    for (int t = 0; t < T_STEPS; ++t) {
        v = fmaf(acc[t] - v, 0.5f, v);
        const float sp = (v >= 1.0f) ? 1.0f : 0.0f;
        v = (sp != 0.0f) ? 0.0f : v;

        float r = sp * w;
        #pragma unroll
        for (int off = 16; off; off >>= 1)
            r += __shfl_down_sync(0xffffffffu, r, off);
        if (lane == 0) sh[t][warp] = r;
    }
    __syncthreads();

    if (warp == 0) {
        float z = bo;
        #pragma unroll
        for (int w8 = 0; w8 < 8; ++w8) z += sh[lane][w8];
        float a = 0.0f, mine = 0.0f;
        #pragma unroll
        for (int t = 0; t < T_STEPS; ++t) {
            a += __shfl_sync(0xffffffffu, z, t);
            if (lane == t) mine = a;
        }
        out[lane * N_BATCH + nb] = mine;
    }
}

// ---------------------------------------------------------------------------
// Host: launch dependent kernels with programmatic stream serialization.
// ---------------------------------------------------------------------------
template<typename... Args>
static void launch_pdl(void (*kern)(Args...), dim3 grid, dim3 block, Args... args)
{
    cudaLaunchConfig_t cfg = {};
    cfg.gridDim = grid;
    cfg.blockDim = block;
    cfg.dynamicSmemBytes = 0;
    cfg.stream = 0;
    cudaLaunchAttribute attr[1];
    attr[0].id = cudaLaunchAttributeProgrammaticStreamSerialization;
    attr[0].val.programmaticStreamSerializationAllowed = 1;
    cfg.attrs = attr;
    cfg.numAttrs = 1;
    cudaLaunchKernelEx(&cfg, kern, args...);
}

extern "C" void kernel_launch(void* const* d_in, const int* in_sizes, int n_in,
                              void* d_out, int out_size)
{
    const float* x      = (const float*)d_in[0];
    const float* W_sdc  = (const float*)d_in[1];
    const float* b_sdc  = (const float*)d_in[2];
    const float* w_syn  = (const float*)d_in[3];
    const float* W_pool = (const float*)d_in[4];
    const float* b_pool = (const float*)d_in[5];
    const float* W_f1   = (const float*)d_in[6];
    const float* b_f1   = (const float*)d_in[7];
    const float* W_f2   = (const float*)d_in[8];
    const float* b_f2   = (const float*)d_in[9];
    const float* W_out  = (const float*)d_in[10];
    const float* b_out  = (const float*)d_in[11];
    float* out = (float*)d_out;

    float* s2 = nullptr; float* h1 = nullptr; float* part = nullptr;
    cudaGetSymbolAddress((void**)&s2, g_s2);
    cudaGetSymbolAddress((void**)&h1, g_h1);
    cudaGetSymbolAddress((void**)&part, g_part);

    const int M = T_STEPS * N_BATCH;  // 512

    // K1: fused SNN core -> g_s2 [T,N,D].  4096 blocks (max parallelism).
    k_snn_core<<<N_BATCH * D_DIM, 256>>>(x, W_sdc, b_sdc, w_syn, W_pool, b_pool);

    // K2: partials of s2 @ W_f1  (M=512, K=256, N=512), S=8, Kc=32 -> 256 blocks
    launch_pdl(k_gemm_splitk_w, dim3(F1_DIM / 128, M / 64, 8), dim3(256),
               (const float*)s2, W_f1, part, M, (int)D_DIM, (int)F1_DIM, 32);

    // K3: reduce(8) + bias + LIF -> h1
    launch_pdl(k_reduce_lif<8>, dim3((N_BATCH * F1_DIM) / 256), dim3(256),
               (const float*)part, b_f1, h1, (int)F1_DIM);

    // K4: partials of h1 @ W_f2  (M=512, K=512, N=256), S=8, Kc=64 -> 256 blocks
    launch_pdl(k_gemm_splitk, dim3(F2_DIM / 64, M / 64, 8), dim3(256),
               (const float*)h1, W_f2, part, M, (int)F1_DIM, (int)F2_DIM, 64);

    // K5: fused reduce(8) + LIF + readout dot + cumsum -> out
    launch_pdl(k_tail<8>, dim3(N_BATCH), dim3(256),
               (const float*)part, b_f2, W_out, b_out, out);
}